// round 16
// baseline (speedup 1.0000x reference)
#include <cuda_runtime.h>
#include <math.h>

#define N_NODES 20000
#define N_EDGES 640000
#define MTILE 64

// Scratch (allocation-free rule: __device__ globals)
__device__ float g_y[N_NODES * 80];       // 6.4 MB  l1-transformed node features
__device__ float g_agg[N_NODES * 192];    // 15.36 MB segment-sum accumulator (L2-resident)

// ---------------------------------------------------------------------------
// f32x2 packed helpers (sm_100+): FFMA2 doubles fp32 FMA throughput.
// ---------------------------------------------------------------------------
__device__ __forceinline__ unsigned long long pack2(float x) {
    unsigned long long r;
    asm("mov.b64 %0, {%1, %1};" : "=l"(r) : "f"(x));
    return r;
}
__device__ __forceinline__ void ffma2(unsigned long long& d,
                                      unsigned long long a,
                                      unsigned long long b) {
    asm("fma.rn.f32x2 %0, %1, %2, %0;" : "+l"(d) : "l"(a), "l"(b));
}
__device__ __forceinline__ void red4(float* p, float a, float b, float c, float d) {
    asm volatile("red.global.add.v4.f32 [%0], {%1,%2,%3,%4};"
                 :: "l"(p), "f"(a), "f"(b), "f"(c), "f"(d) : "memory");
}

// ---------------------------------------------------------------------------
// Node transform: out = c_s * s, g_y = y.  16 nodes per 256-thread block;
// outputs strided (j = q + 16t) for uniform branches + high ILP.
// ---------------------------------------------------------------------------
__global__ void __launch_bounds__(256) node_kernel(
        const float* __restrict__ node_input,
        const float* __restrict__ node_attr,
        const float* __restrict__ Wsc0, const float* __restrict__ Wsc1,
        const float* __restrict__ Wl10, const float* __restrict__ Wl11,
        float* __restrict__ out) {
    __shared__ float s0[32 * 32], l0[32 * 32], s1[16 * 16], l1[16 * 16];
    __shared__ float sx[16 * 80];
    __shared__ float sa[16];
    for (int i = threadIdx.x; i < 1024; i += 256) { s0[i] = Wsc0[i]; l0[i] = Wl10[i]; }
    for (int i = threadIdx.x; i < 256;  i += 256) { s1[i] = Wsc1[i]; l1[i] = Wl11[i]; }

    int n0 = blockIdx.x * 16;
    int nodes = N_NODES - n0; if (nodes > 16) nodes = 16;
    for (int i = threadIdx.x; i < nodes * 20; i += 256)
        ((float4*)sx)[i] = ((const float4*)(node_input + (long long)n0 * 80))[i];
    if (threadIdx.x < nodes) sa[threadIdx.x] = node_attr[n0 + threadIdx.x];
    __syncthreads();

    int ln = threadIdx.x >> 4;      // local node 0..15
    int q  = threadIdx.x & 15;      // outputs j = q + 16t, t=0..4
    if (ln >= nodes) return;
    const float* x = sx + ln * 80;
    float a = sa[ln];
    const float c_s = 0.3826834323650898f;   // sin(pi/8)
    float* outr = out + (long long)(n0 + ln) * 80;
    float* yr   = g_y + (long long)(n0 + ln) * 80;

    // scalar outputs j = q, q+16  (both < 32)
    {
        float as0 = 0.f, al0 = 0.f, as1 = 0.f, al1 = 0.f;
#pragma unroll
        for (int u = 0; u < 32; u++) {
            float xv = x[u];
            as0 += xv * s0[u * 32 + q];
            al0 += xv * l0[u * 32 + q];
            as1 += xv * s0[u * 32 + q + 16];
            al1 += xv * l0[u * 32 + q + 16];
        }
        const float inv = 0.17677669529663687f;  // 1/sqrt(32)
        outr[q]      = c_s * as0 * inv * a;
        yr[q]        = al0 * inv * a;
        outr[q + 16] = c_s * as1 * inv * a;
        yr[q + 16]   = al1 * inv * a;
    }
    // vector outputs j = q+32, q+48, q+64  (all >= 32)
    {
        float zs[3] = {0.f, 0.f, 0.f}, zl[3] = {0.f, 0.f, 0.f};
        int v[3], i3[3];
#pragma unroll
        for (int t = 0; t < 3; t++) {
            int g = q + 16 * t;       // 0..47
            v[t] = g / 3; i3[t] = g - 3 * v[t];
        }
#pragma unroll
        for (int u = 0; u < 16; u++) {
#pragma unroll
            for (int t = 0; t < 3; t++) {
                float xv = x[32 + u * 3 + i3[t]];
                zs[t] += xv * s1[u * 16 + v[t]];
                zl[t] += xv * l1[u * 16 + v[t]];
            }
        }
#pragma unroll
        for (int t = 0; t < 3; t++) {
            int j = q + 32 + 16 * t;
            outr[j] = c_s * zs[t] * 0.25f * a;   // 1/sqrt(16)
            yr[j]   = zl[t] * 0.25f * a;
        }
    }
}

// ---------------------------------------------------------------------------
// Message value helper: 4 contiguous fields starting at f0 (f0 % 4 == 0).
// Regions (float4-pure): [0,32) m_a, [32,48) m_d, [48,144) m_b, [144,192) m_c.
// BOTH we and ye now point to shared memory.
// ---------------------------------------------------------------------------
__device__ __forceinline__ float4 msg_val4(int f0,
        const float* we, const float* ye,
        float ea0, float e1x, float e1y, float e1z) {
    float4 r;
    if (f0 < 32) {                       // m_a: w_a[f]*y0[f]*e0
        float4 w4 = *(const float4*)(we + f0);
        float4 y4 = *(const float4*)(ye + f0);
        r.x = w4.x * y4.x * ea0; r.y = w4.y * y4.y * ea0;
        r.z = w4.z * y4.z * ea0; r.w = w4.w * y4.w * ea0;
    } else if (f0 < 48) {                // m_d: w_d[u]*dot(y1[u],e1)  (1/sqrt3 in w)
        int u0 = f0 - 32;
        float4 w4 = *(const float4*)(we + 80 + u0);
        float4 ya = *(const float4*)(ye + 32 + 3 * u0);
        float4 yb = *(const float4*)(ye + 36 + 3 * u0);
        float4 yc = *(const float4*)(ye + 40 + 3 * u0);
        float t[12] = {ya.x, ya.y, ya.z, ya.w, yb.x, yb.y, yb.z, yb.w,
                       yc.x, yc.y, yc.z, yc.w};
        r.x = w4.x * (t[0] * e1x + t[1]  * e1y + t[2]  * e1z);
        r.y = w4.y * (t[3] * e1x + t[4]  * e1y + t[5]  * e1z);
        r.z = w4.z * (t[6] * e1x + t[7]  * e1y + t[8]  * e1z);
        r.w = w4.w * (t[9] * e1x + t[10] * e1y + t[11] * e1z);
    } else if (f0 < 144) {               // m_b: w_b[c]*y0[c]*e1[i], g=f-48, c=g/3
        float v[4];
#pragma unroll
        for (int q = 0; q < 4; q++) {
            int g = f0 - 48 + q;
            int c = g / 3, i = g - 3 * c;
            float e1v = (i == 0) ? e1x : ((i == 1) ? e1y : e1z);
            v[q] = we[32 + c] * ye[c] * e1v;
        }
        r.x = v[0]; r.y = v[1]; r.z = v[2]; r.w = v[3];
    } else {                             // m_c: w_c[g/3]*ye[32+g]*e0
        int g0 = f0 - 144;
        float4 y4 = *(const float4*)(ye + 32 + g0);
        float yy[4] = {y4.x, y4.y, y4.z, y4.w};
        float v[4];
#pragma unroll
        for (int q = 0; q < 4; q++) v[q] = we[64 + (g0 + q) / 3] * yy[q] * ea0;
        r.x = v[0]; r.y = v[1]; r.z = v[2]; r.w = v[3];
    }
    return r;
}

// ---------------------------------------------------------------------------
// Fused edge kernel v2: 64 edges/CTA, 256 threads, ~71 KB smem (3 CTAs/SM).
// Phase 0 prefetches y[src] rows (coalesced LDG.128) into registers — the
// MLP compute covers the latency — then stores to sY. The message phase
// reads w AND y from smem and fires no-return red.v4 atomics.
// smem (floats): sW0 640 | sW1 6144 | sY 5120 | U 6144
//   U phases 1-2: sHT (64x68=4352) + sES (640); U phase 3: sWo (64x96=6144)
// ---------------------------------------------------------------------------
__global__ void __launch_bounds__(256) edge_kernel(
        const float* __restrict__ edge_scalars,
        const float* __restrict__ edge_attr,
        const int* __restrict__ edge_index,
        const float* __restrict__ Wfc0,
        const float* __restrict__ Wfc1) {
    extern __shared__ float sm[];
    float* sW0 = sm;                 // 640
    float* sW1 = sm + 640;           // 6144
    float* sY  = sm + 6784;          // 5120
    float* U   = sm + 11904;         // 6144 union
    float* sHT = U;                  // 64 x 68 (phases 1-2)
    float* sES = U + 4352;           // 640     (phase 1)
    float* sWo = U;                  // 64 x 96 (phase 3)

    const int tid = threadIdx.x;
    const int e0 = blockIdx.x * MTILE;

    // ---- phase 0: stage weights + edge scalars; prefetch y rows ----
    const float invs10 = 0.31622776601683794f;        // 1/sqrt(10)
    for (int i = tid; i < 640; i += 256) sW0[i] = Wfc0[i] * invs10;
    const float w1scale = 0.02209708691207961f;       // 1/sqrt(64*32)
    const float invs3   = 0.5773502691896258f;        // 1/sqrt(3)
    for (int i = tid; i < 6144; i += 256) {
        int col = i % 96;
        sW1[i] = Wfc1[i] * (col >= 80 ? w1scale * invs3 : w1scale);
    }
    for (int i = tid; i < MTILE * 10; i += 256) sES[i] = edge_scalars[e0 * 10 + i];

    // y prefetch: 4 threads per edge, 5 float4 each (one 320B row per quad)
    const int ple = tid >> 2;            // edge 0..63
    const int pq  = tid & 3;             // quad lane
    float4 yreg[5];
    {
        int src = __ldg(edge_index + e0 + ple);
        const float* yrow = g_y + (long long)src * 80 + pq * 20;
#pragma unroll
        for (int j = 0; j < 5; j++)
            yreg[j] = __ldg((const float4*)(yrow + j * 4));
    }
    __syncthreads();

    // ---- phase 1: layer 1 (4 threads/edge, 16 h-cols each) ----
    {
        int le = tid >> 2;
        int c0 = (tid & 3) * 16;
        float es[10];
#pragma unroll
        for (int k = 0; k < 10; k++) es[k] = sES[le * 10 + k];
        float acc[16];
#pragma unroll
        for (int j = 0; j < 16; j++) acc[j] = 0.f;
#pragma unroll
        for (int k = 0; k < 10; k++) {
            float x = es[k];
#pragma unroll
            for (int j = 0; j < 16; j++) acc[j] += x * sW0[k * 64 + c0 + j];
        }
#pragma unroll
        for (int j = 0; j < 16; j++) {
            float aa = acc[j];
            sHT[(c0 + j) * 68 + le] = aa / (1.0f + __expf(-aa));
        }
    }
    // commit prefetched y to sY (LDGs have long completed under layer-1)
    {
        float* yd = sY + ple * 80 + pq * 20;
#pragma unroll
        for (int j = 0; j < 5; j++)
            *(float4*)(yd + j * 4) = yreg[j];
    }
    __syncthreads();

    // ---- phase 2: layer 2 (thread = 2 edges x 12 cols, 6 f32x2 pairs) ----
    unsigned long long acc[2][6];
    {
        int eb = (tid >> 3) * 2;     // edge base (0..62)
        int c0 = (tid & 7) * 12;     // col base  (0..84)
#pragma unroll
        for (int e = 0; e < 2; e++)
#pragma unroll
            for (int p = 0; p < 6; p++) acc[e][p] = 0ull;

#pragma unroll 4
        for (int k = 0; k < 64; k++) {
            float2 h2 = *(const float2*)&sHT[k * 68 + eb];
            unsigned long long hp0 = pack2(h2.x);
            unsigned long long hp1 = pack2(h2.y);
            const float* wr = &sW1[k * 96 + c0];
#pragma unroll
            for (int p = 0; p < 6; p++) {
                unsigned long long wp = *(const unsigned long long*)&wr[2 * p];
                ffma2(acc[0][p], hp0, wp);
                ffma2(acc[1][p], hp1, wp);
            }
        }
    }
    __syncthreads();   // done reading sHT; U becomes sWo

    {
        int eb = (tid >> 3) * 2;
        int c0 = (tid & 7) * 12;
#pragma unroll
        for (int e = 0; e < 2; e++) {
            float* dst = sWo + (eb + e) * 96 + c0;
#pragma unroll
            for (int pp = 0; pp < 3; pp++) {
                ulonglong2 v;
                v.x = acc[e][2 * pp];
                v.y = acc[e][2 * pp + 1];
                *(ulonglong2*)(dst + 4 * pp) = v;
            }
        }
    }
    __syncthreads();

    // ---- phase 3: message + scatter, warp-per-edge, 8 edges per warp ----
    const int warp = tid >> 5;
    const int lane = tid & 31;
    for (int t = warp; t < MTILE; t += 8) {
        const int e = e0 + t;
        int dst = __ldg(edge_index + N_EDGES + e);
        const float* we = sWo + t * 96;
        const float* ye = sY + t * 80;
        float4 ea = __ldg((const float4*)(edge_attr + e * 4));
        float* aggr = g_agg + (long long)dst * 192;

        {   // fields 0..127
            int f0 = lane * 4;
            float4 v = msg_val4(f0, we, ye, ea.x, ea.y, ea.z, ea.w);
            red4(aggr + f0, v.x, v.y, v.z, v.w);
        }
        if (lane < 16) {   // fields 128..191
            int f0 = 128 + lane * 4;
            float4 v = msg_val4(f0, we, ye, ea.x, ea.y, ea.z, ea.w);
            red4(aggr + f0, v.x, v.y, v.z, v.w);
        }
    }
}

// ---------------------------------------------------------------------------
// Final: out += c_x * (agg @ W_l2) / sqrt(48).  Strided outputs (j = q+16t),
// 5 independent accumulators, FULL 48-term reduction for every output.
// ---------------------------------------------------------------------------
__global__ void __launch_bounds__(256) final_kernel(
        const float* __restrict__ Wl20,
        const float* __restrict__ Wl21,
        float* __restrict__ out) {
    __shared__ float sW0[48 * 32];
    __shared__ float sW1[48 * 16];
    __shared__ float sa[16 * 192];
    const float sc = 0.9238795325112867f * 0.14433756729740643f;  // cos(pi/8)/sqrt(48)
    for (int i = threadIdx.x; i < 48 * 32; i += 256) sW0[i] = Wl20[i] * sc;
    for (int i = threadIdx.x; i < 48 * 16; i += 256) sW1[i] = Wl21[i] * sc;

    int n0 = blockIdx.x * 16;
    int nodes = N_NODES - n0; if (nodes > 16) nodes = 16;
    for (int i = threadIdx.x; i < nodes * 48; i += 256)
        ((float4*)sa)[i] = ((const float4*)(g_agg + (long long)n0 * 192))[i];
    __syncthreads();

    int ln = threadIdx.x >> 4;
    int q  = threadIdx.x & 15;
    if (ln >= nodes) return;
    const float* a  = sa + ln * 192;
    const float* a1 = a + 48;
    float* outr = out + (long long)(n0 + ln) * 80;

    float z0 = 0.f, z1 = 0.f, z2 = 0.f, z3 = 0.f, z4 = 0.f;
    int v2, i2, v3, i3, v4, i4;
    { int g = q;      v2 = g / 3; i2 = g - 3 * v2; }
    { int g = q + 16; v3 = g / 3; i3 = g - 3 * v3; }
    { int g = q + 32; v4 = g / 3; i4 = g - 3 * v4; }
#pragma unroll
    for (int u = 0; u < 48; u++) {
        float au = a[u];
        z0 += au * sW0[u * 32 + q];
        z1 += au * sW0[u * 32 + q + 16];
        z2 += a1[u * 3 + i2] * sW1[u * 16 + v2];
        z3 += a1[u * 3 + i3] * sW1[u * 16 + v3];
        z4 += a1[u * 3 + i4] * sW1[u * 16 + v4];
    }
    outr[q]      += z0;
    outr[q + 16] += z1;
    outr[q + 32] += z2;
    outr[q + 48] += z3;
    outr[q + 64] += z4;
}

// ---------------------------------------------------------------------------
extern "C" void kernel_launch(void* const* d_in, const int* in_sizes, int n_in,
                              void* d_out, int out_size) {
    const float* node_input   = (const float*)d_in[0];
    const float* node_attr    = (const float*)d_in[1];
    const float* edge_attr    = (const float*)d_in[2];
    const float* edge_scalars = (const float*)d_in[3];
    const float* Wsc0 = (const float*)d_in[4];
    const float* Wsc1 = (const float*)d_in[5];
    const float* Wl10 = (const float*)d_in[6];
    const float* Wl11 = (const float*)d_in[7];
    const float* Wfc0 = (const float*)d_in[8];
    const float* Wfc1 = (const float*)d_in[9];
    const float* Wl20 = (const float*)d_in[10];
    const float* Wl21 = (const float*)d_in[11];
    const int*   edge_index = (const int*)d_in[12];
    float* out = (float*)d_out;

    void* agg_ptr = nullptr;
    cudaGetSymbolAddress(&agg_ptr, g_agg);
    cudaMemsetAsync(agg_ptr, 0, (size_t)N_NODES * 192 * sizeof(float));

    node_kernel<<<(N_NODES + 15) / 16, 256>>>(node_input, node_attr,
                                              Wsc0, Wsc1, Wl10, Wl11, out);

    const int smem_bytes = (640 + 6144 + 5120 + 6144) * 4;   // 72192 B
    cudaFuncSetAttribute(edge_kernel, cudaFuncAttributeMaxDynamicSharedMemorySize,
                         smem_bytes);
    edge_kernel<<<N_EDGES / MTILE, 256, smem_bytes>>>(edge_scalars, edge_attr,
                                                      edge_index, Wfc0, Wfc1);
    final_kernel<<<(N_NODES + 15) / 16, 256>>>(Wl20, Wl21, out);
}